// round 3
// baseline (speedup 1.0000x reference)
#include <cuda_runtime.h>
#include <math.h>

#define NB 8

__constant__ float c_START_Y[NB] = {0.1f, 0.2f, 0.3f, 0.4f, 0.5f, 0.6f, 0.7f, 0.8f};
__constant__ float c_START_X[NB] = {0.8f, 0.7f, 0.6f, 0.5f, 0.4f, 0.3f, 0.2f, 0.1f};
__constant__ int   c_SIDE[NB]    = {1, 0, 1, 0, 1, 0, 1, 0};

#define MAX_B 4096
__device__ float g_params[NB * MAX_B * 5];

__device__ __forceinline__ float sigmoidf_(float v) {
    return 1.0f / (1.0f + __expf(-v));
}

// ---------------- f32x2 packed helpers (Blackwell FFMA2) --------------------
typedef unsigned long long ull;
__device__ __forceinline__ ull pk2(float x, float y) {
    ull r; asm("mov.b64 %0, {%1,%2};" : "=l"(r) : "f"(x), "f"(y)); return r;
}
__device__ __forceinline__ void upk2(float& x, float& y, ull v) {
    asm("mov.b64 {%0,%1}, %2;" : "=f"(x), "=f"(y) : "l"(v));
}
__device__ __forceinline__ ull fma2(ull a, ull b, ull c) {
    ull d; asm("fma.rn.f32x2 %0, %1, %2, %3;" : "=l"(d) : "l"(a), "l"(b), "l"(c)); return d;
}
__device__ __forceinline__ ull add2(ull a, ull b) {
    ull d; asm("add.rn.f32x2 %0, %1, %2;" : "=l"(d) : "l"(a), "l"(b)); return d;
}

// ---------------------------------------------------------------------------
// Encode: per-blob MLP -> quadratic-form splat coefficients (unchanged, passes)
// ---------------------------------------------------------------------------
__global__ void encode_kernel(const float* __restrict__ positions,
                              const float* __restrict__ W1, const float* __restrict__ b1,
                              const float* __restrict__ W2, const float* __restrict__ b2,
                              const float* __restrict__ W3, const float* __restrict__ b3,
                              const float* __restrict__ scale_ptr, int B)
{
    const int i  = blockIdx.y;
    const int ty = threadIdx.y;
    const int k  = threadIdx.x;
    const int b  = blockIdx.x * 4 + ty;
    const bool valid = (b < B);

    __shared__ float sh_h[4][64];
    __shared__ float sh_bd[4][5];

    float h = 0.0f;
    if (valid) {
        const float* p = positions + (size_t)b * 6 + (c_SIDE[i] ? 0 : 3);
        float p0 = p[0] * 100.0f, p1 = p[1] * 100.0f, p2 = p[2] * 100.0f;
        const float* w1 = W1 + (size_t)i * 3 * 64;
        h = fmaf(p0, w1[k], fmaf(p1, w1[64 + k], fmaf(p2, w1[128 + k], b1[i * 64 + k])));
        h = fmaxf(h, 0.0f);
    }
    sh_h[ty][k] = h;
    __syncthreads();

    float acc = b2[i * 64 + k];
    {
        const float* w2 = W2 + (size_t)i * 64 * 64 + k;
        #pragma unroll 8
        for (int hh = 0; hh < 64; hh++)
            acc = fmaf(sh_h[ty][hh], w2[hh * 64], acc);
        acc = fmaxf(acc, 0.0f);
    }
    __syncthreads();
    sh_h[ty][k] = acc;
    __syncthreads();

    if (k < 5) {
        float o = b3[i * 5 + k];
        const float* w3 = W3 + (size_t)i * 64 * 5 + k;
        #pragma unroll 8
        for (int hh = 0; hh < 64; hh++)
            o = fmaf(sh_h[ty][hh], w3[hh * 5], o);
        sh_bd[ty][k] = o;
    }
    __syncthreads();

    if (k == 0 && valid) {
        float bd0 = sh_bd[ty][0], bd1 = sh_bd[ty][1], bd2 = sh_bd[ty][2];
        float bd3 = sh_bd[ty][3], bd4 = sh_bd[ty][4];
        float scale = *scale_ptr;

        float y  = sigmoidf_(bd0) + c_START_Y[i];
        float x  = sigmoidf_(bd1) + c_START_X[i];
        float s  = (bd2 + 0.05f) * scale;
        float a  = 0.5f + sigmoidf_(bd3) * 1.5f;
        float th = sigmoidf_(bd4) * 3.14159265358979323846f;

        float sa = s * a + 1e-6f;
        float sb = s / (a + 1e-6f) + 1e-6f;
        float A  = 0.5f / (sa * sa);
        float Bq = 0.5f / (sb * sb);

        float sn, c;
        sincosf(th, &sn, &c);

        const float L = 1.4426950408889634f;
        float al = -L * (A * c * c + Bq * sn * sn);
        float be = -L * (A * sn * sn + Bq * c * c);
        float ga = -2.0f * L * (A - Bq) * c * sn;

        float* o = g_params + ((size_t)i * B + b) * 5;
        o[0] = y; o[1] = x; o[2] = al; o[3] = be; o[4] = ga;
    }
}

// ---------------------------------------------------------------------------
// Fast splat for T = NC*64 (warp = one row; lane = 2 adjacent pixels, f32x2).
// Per (row, blob): analytic alive/poly column intervals (concave quadratic).
// Per 64-col chunk (warp-uniform): dead -> img=0 / poly -> deg-5 FMA exp2 /
// mufu -> ex2.approx.
// ---------------------------------------------------------------------------

// deg-5 economized Taylor of 0.5*2^u on u in [-1,1]  (abs err ~1e-5)
#define C0H 0.5000024068f
#define C1H 0.3465735903f
#define C2H 0.1200699310f
#define C3H 0.0277520543f
#define C4H 0.0049245900f
#define C5H 0.0006666779f

#define TH_DEAD (-36.0f)
#define TH_POLY (-2.0f)

template<int NC>
__global__ void __launch_bounds__(256) splat_fast(float* __restrict__ out,
                                                  int B, int T, float invT)
{
    const int b    = blockIdx.y;
    const int tid  = threadIdx.x;
    const int lane = tid & 31;
    const int r    = tid >> 5;
    const int row  = blockIdx.x * 8 + r;

    __shared__ float sp[NB * 5];
    if (tid < NB * 5) {
        int i = tid / 5, f = tid - i * 5;
        sp[tid] = g_params[((size_t)i * B + b) * 5 + f];
    }
    __syncthreads();
    if (row >= T) return;

    const float rowc = ((float)row + 0.5f) * invT;

    // per-blob quadratic coefficients e(w) = K2 w^2 + K1 w + K0  (K2 < 0)
    float K2[NB], K1[NB], K0[NB];
    #pragma unroll
    for (int i = 0; i < NB; i++) {
        float y  = sp[i * 5 + 0];
        float x  = sp[i * 5 + 1];
        float al = sp[i * 5 + 2];
        float be = sp[i * 5 + 3];
        float ga = sp[i * 5 + 4];
        float dy = rowc - y;
        K2[i] = be;
        K1[i] = fmaf(ga, dy, -2.0f * be * x);
        float m = fmaf(al, dy, -(ga * x));
        K0[i] = fmaf(m, dy, be * x * x);
    }

    // chunk classification masks: bit (i*NC + j). Lane i<NB handles blob i.
    unsigned deadc = 0, polyc = 0;
    if (lane < NB) {
        const int i = lane;
        float y  = sp[i * 5 + 0];
        float x  = sp[i * 5 + 1];
        float al = sp[i * 5 + 2];
        float be = sp[i * 5 + 3];
        float ga = sp[i * 5 + 4];
        float dy = rowc - y;
        float k2 = be;
        float k1 = fmaf(ga, dy, -2.0f * be * x);
        float m  = fmaf(al, dy, -(ga * x));
        float k0 = fmaf(m, dy, be * x * x);

        float i2 = 0.5f / k2;                       // negative
        float dd = k1 * k1 - 4.0f * k2 * (k0 - TH_DEAD);
        float dp = k1 * k1 - 4.0f * k2 * (k0 - TH_POLY);
        float rdlo = 3.0e37f, rdhi = -3.0e37f;      // empty alive interval
        if (dd > 0.0f) {
            float sd = sqrtf(dd);
            rdlo = (-k1 + sd) * i2;
            rdhi = (-k1 - sd) * i2;
        }
        float rplo = 3.0e37f, rphi = -3.0e37f;      // empty poly interval
        if (dp > 0.0f) {
            float sq = sqrtf(dp);
            rplo = (-k1 + sq) * i2;
            rphi = (-k1 - sq) * i2;
        }
        #pragma unroll
        for (int j = 0; j < NC; j++) {
            float wa = ((float)(j * 64) + 0.5f) * invT;
            float wb = ((float)(j * 64) + 63.5f) * invT;
            bool dead = (wb < rdlo) || (wa > rdhi);
            bool poly = (wa >= rplo) && (wb <= rphi);
            if (dead) deadc |= 1u << (i * NC + j);
            else if (poly) polyc |= 1u << (i * NC + j);
        }
    }
    const unsigned deadm = __reduce_or_sync(0xffffffffu, deadc);
    const unsigned polym = __reduce_or_sync(0xffffffffu, polyc);

    // pack coefficients for f32x2
    ull K2p[NB], K1p[NB], K0p[NB];
    #pragma unroll
    for (int i = 0; i < NB; i++) {
        K2p[i] = pk2(K2[i], K2[i]);
        K1p[i] = pk2(K1[i], K1[i]);
        K0p[i] = pk2(K0[i], K0[i]);
    }

    const ull ONE2 = pk2(1.0f, 1.0f);
    const ull P5 = pk2(C5H, C5H), P4 = pk2(C4H, C4H), P3 = pk2(C3H, C3H);
    const ull P2 = pk2(C2H, C2H), P1 = pk2(C1H, C1H), P0 = pk2(C0H, C0H);

    float* orow = out + ((size_t)b * T + row) * T;

    #pragma unroll
    for (int j = 0; j < NC; j++) {
        float w0 = ((float)(j * 64 + 2 * lane) + 0.5f) * invT;
        ull w   = pk2(w0, w0 + invT);
        ull img = 0ull;   // (0.0f, 0.0f)

        #pragma unroll
        for (int i = 0; i < NB; i++) {
            const unsigned bit = 1u << (i * NC + j);
            if (deadm & bit) { img = 0ull; continue; }
            ull e = fma2(fma2(K2p[i], w, K1p[i]), w, K0p[i]);
            ull cur;
            if (polym & bit) {
                ull u = add2(e, ONE2);
                ull p = fma2(P5, u, P4);
                p = fma2(p, u, P3);
                p = fma2(p, u, P2);
                p = fma2(p, u, P1);
                cur = fma2(p, u, P0);
            } else {
                float ex, ey, cx, cy;
                upk2(ex, ey, e);
                asm("ex2.approx.ftz.f32 %0, %1;" : "=f"(cx) : "f"(ex));
                asm("ex2.approx.ftz.f32 %0, %1;" : "=f"(cy) : "f"(ey));
                cur = pk2(cx, cy);
            }
            img = fma2(img, cur, cur);
        }

        float ix, iy;
        upk2(ix, iy, img);
        reinterpret_cast<float2*>(orow + j * 64)[lane] = make_float2(ix, iy);
    }
}

// ---------------------------------------------------------------------------
// Generic fallback splat (round-2 kernel, known correct for any T).
// ---------------------------------------------------------------------------
__global__ void __launch_bounds__(256) splat_kernel(float* __restrict__ out,
                                                    int B, int T, float invT)
{
    const int b    = blockIdx.y;
    const int tid  = threadIdx.x;
    const int lane = tid & 31;
    const int r    = tid >> 5;
    const int row  = blockIdx.x * 8 + r;

    __shared__ float sp[NB * 5];
    if (tid < NB * 5) {
        int i = tid / 5, f = tid - i * 5;
        sp[tid] = g_params[((size_t)i * B + b) * 5 + f];
    }
    __syncthreads();
    if (row >= T) return;

    const float rowc = ((float)row + 0.5f) * invT;

    float K2[NB], K1[NB], K0[NB];
    #pragma unroll
    for (int i = 0; i < NB; i++) {
        float y  = sp[i * 5 + 0];
        float x  = sp[i * 5 + 1];
        float al = sp[i * 5 + 2];
        float be = sp[i * 5 + 3];
        float ga = sp[i * 5 + 4];
        float dy = rowc - y;
        K2[i] = be;
        K1[i] = fmaf(ga, dy, -2.0f * be * x);
        float m = fmaf(al, dy, -(ga * x));
        K0[i] = fmaf(m, dy, be * x * x);
    }

    float* orow = out + ((size_t)b * T + row) * T;
    const int nj = (T + 31) >> 5;

    for (int j = 0; j < nj; j++) {
        int col = lane + (j << 5);
        if (col >= T) break;
        float w = ((float)col + 0.5f) * invT;
        float img = 0.0f;
        #pragma unroll
        for (int i = 0; i < NB; i++) {
            float e = fmaf(fmaf(K2[i], w, K1[i]), w, K0[i]);
            float cur;
            asm("ex2.approx.ftz.f32 %0, %1;" : "=f"(cur) : "f"(e));
            img = fmaf(img, cur, cur);
        }
        orow[col] = img;
    }
}

// ---------------------------------------------------------------------------
extern "C" void kernel_launch(void* const* d_in, const int* in_sizes, int n_in,
                              void* d_out, int out_size)
{
    const float* positions = (const float*)d_in[0];
    const float* W1 = (const float*)d_in[1];
    const float* b1 = (const float*)d_in[2];
    const float* W2 = (const float*)d_in[3];
    const float* b2 = (const float*)d_in[4];
    const float* W3 = (const float*)d_in[5];
    const float* b3 = (const float*)d_in[6];
    const float* scale = (const float*)d_in[n_in - 1];

    int B = in_sizes[0] / 6;
    if (B > MAX_B) B = MAX_B;
    int T = (int)(sqrt((double)out_size / (double)B) + 0.5);
    float invT = 1.0f / (float)T;

    dim3 egrid((B + 3) / 4, NB);
    dim3 eblock(64, 4);
    encode_kernel<<<egrid, eblock>>>(positions, W1, b1, W2, b2, W3, b3, scale, B);

    dim3 sgrid((T + 7) / 8, B);
    if (T == 256)
        splat_fast<4><<<sgrid, 256>>>((float*)d_out, B, T, invT);
    else if (T == 128)
        splat_fast<2><<<sgrid, 256>>>((float*)d_out, B, T, invT);
    else
        splat_kernel<<<sgrid, 256>>>((float*)d_out, B, T, invT);
}

// round 4
// speedup vs baseline: 1.1993x; 1.1993x over previous
#include <cuda_runtime.h>
#include <math.h>

#define NB 8

__constant__ float c_START_Y[NB] = {0.1f, 0.2f, 0.3f, 0.4f, 0.5f, 0.6f, 0.7f, 0.8f};
__constant__ float c_START_X[NB] = {0.8f, 0.7f, 0.6f, 0.5f, 0.4f, 0.3f, 0.2f, 0.1f};
__constant__ int   c_SIDE[NB]    = {1, 0, 1, 0, 1, 0, 1, 0};

#define MAX_B 4096
__device__ float g_params[NB * MAX_B * 5];

__device__ __forceinline__ float sigmoidf_(float v) {
    return 1.0f / (1.0f + __expf(-v));
}

// ---------------- f32x2 packed helpers (Blackwell FFMA2) --------------------
typedef unsigned long long ull;
__device__ __forceinline__ ull pk2(float x, float y) {
    ull r; asm("mov.b64 %0, {%1,%2};" : "=l"(r) : "f"(x), "f"(y)); return r;
}
__device__ __forceinline__ void upk2(float& x, float& y, ull v) {
    asm("mov.b64 {%0,%1}, %2;" : "=f"(x), "=f"(y) : "l"(v));
}
__device__ __forceinline__ ull fma2(ull a, ull b, ull c) {
    ull d; asm("fma.rn.f32x2 %0, %1, %2, %3;" : "=l"(d) : "l"(a), "l"(b), "l"(c)); return d;
}

// ---------------------------------------------------------------------------
// Encode: per-blob MLP -> quadratic-form splat coefficients (unchanged, passes)
// ---------------------------------------------------------------------------
__global__ void encode_kernel(const float* __restrict__ positions,
                              const float* __restrict__ W1, const float* __restrict__ b1,
                              const float* __restrict__ W2, const float* __restrict__ b2,
                              const float* __restrict__ W3, const float* __restrict__ b3,
                              const float* __restrict__ scale_ptr, int B)
{
    const int i  = blockIdx.y;
    const int ty = threadIdx.y;
    const int k  = threadIdx.x;
    const int b  = blockIdx.x * 4 + ty;
    const bool valid = (b < B);

    __shared__ float sh_h[4][64];
    __shared__ float sh_bd[4][5];

    float h = 0.0f;
    if (valid) {
        const float* p = positions + (size_t)b * 6 + (c_SIDE[i] ? 0 : 3);
        float p0 = p[0] * 100.0f, p1 = p[1] * 100.0f, p2 = p[2] * 100.0f;
        const float* w1 = W1 + (size_t)i * 3 * 64;
        h = fmaf(p0, w1[k], fmaf(p1, w1[64 + k], fmaf(p2, w1[128 + k], b1[i * 64 + k])));
        h = fmaxf(h, 0.0f);
    }
    sh_h[ty][k] = h;
    __syncthreads();

    float acc = b2[i * 64 + k];
    {
        const float* w2 = W2 + (size_t)i * 64 * 64 + k;
        #pragma unroll 8
        for (int hh = 0; hh < 64; hh++)
            acc = fmaf(sh_h[ty][hh], w2[hh * 64], acc);
        acc = fmaxf(acc, 0.0f);
    }
    __syncthreads();
    sh_h[ty][k] = acc;
    __syncthreads();

    if (k < 5) {
        float o = b3[i * 5 + k];
        const float* w3 = W3 + (size_t)i * 64 * 5 + k;
        #pragma unroll 8
        for (int hh = 0; hh < 64; hh++)
            o = fmaf(sh_h[ty][hh], w3[hh * 5], o);
        sh_bd[ty][k] = o;
    }
    __syncthreads();

    if (k == 0 && valid) {
        float bd0 = sh_bd[ty][0], bd1 = sh_bd[ty][1], bd2 = sh_bd[ty][2];
        float bd3 = sh_bd[ty][3], bd4 = sh_bd[ty][4];
        float scale = *scale_ptr;

        float y  = sigmoidf_(bd0) + c_START_Y[i];
        float x  = sigmoidf_(bd1) + c_START_X[i];
        float s  = (bd2 + 0.05f) * scale;
        float a  = 0.5f + sigmoidf_(bd3) * 1.5f;
        float th = sigmoidf_(bd4) * 3.14159265358979323846f;

        float sa = s * a + 1e-6f;
        float sb = s / (a + 1e-6f) + 1e-6f;
        float A  = 0.5f / (sa * sa);
        float Bq = 0.5f / (sb * sb);

        float sn, c;
        sincosf(th, &sn, &c);

        const float L = 1.4426950408889634f;
        float al = -L * (A * c * c + Bq * sn * sn);
        float be = -L * (A * sn * sn + Bq * c * c);
        float ga = -2.0f * L * (A - Bq) * c * sn;

        float* o = g_params + ((size_t)i * B + b) * 5;
        o[0] = y; o[1] = x; o[2] = al; o[3] = be; o[4] = ga;
    }
}

// ---------------------------------------------------------------------------
// Splat, blob-outer, row-resident. T = NC*64. warp = row; lane owns NC f32x2
// pixel-pairs (cols chunk*64 + 2*lane). Per (row,blob): dead/poly/mufu mode,
// classified once (lane-parallel). Dead blobs reset img -> start at istart.
// ---------------------------------------------------------------------------

// deg-5 economized poly: P(u) ~= 0.5 * 2^u on u in [-1,1]; cur = P(e+1) = 2^e
#define C0H 0.5000024068f
#define C1H 0.3465735903f
#define C2H 0.1200699310f
#define C3H 0.0277520543f
#define C4H 0.0049245900f
#define C5H 0.0006666779f

#define TH_DEAD (-36.0f)
#define TH_POLY (-2.0f)

template<int NC>
__global__ void __launch_bounds__(256) splat_fast(float* __restrict__ out,
                                                  int B, int T, float invT)
{
    const int b    = blockIdx.y;
    const int tid  = threadIdx.x;
    const int lane = tid & 31;
    const int r    = tid >> 5;
    const int row  = blockIdx.x * 8 + r;

    __shared__ float sp[NB * 5];
    if (tid < NB * 5) {
        int i = tid / 5, f = tid - i * 5;
        sp[tid] = g_params[((size_t)i * B + b) * 5 + f];
    }
    __syncthreads();
    if (row >= T) return;

    const float rowc = ((float)row + 0.5f) * invT;

    // per-blob row quadratic e(w) = K2 w^2 + K1 w + K0  (K2 < 0), uniform in warp
    float K2[NB], K1[NB], K0[NB];
    #pragma unroll
    for (int i = 0; i < NB; i++) {
        float y  = sp[i * 5 + 0];
        float x  = sp[i * 5 + 1];
        float al = sp[i * 5 + 2];
        float be = sp[i * 5 + 3];
        float ga = sp[i * 5 + 4];
        float dy = rowc - y;
        K2[i] = be;
        K1[i] = fmaf(ga, dy, -2.0f * be * x);
        float m = fmaf(al, dy, -(ga * x));
        K0[i] = fmaf(m, dy, be * x * x);
    }

    // ---- lane-parallel classification: lane i (<8) classifies blob i ----
    bool dead = false, poly = false;
    float lo = -3.0e37f, hi = 3.0e37f;
    if (lane < NB) {
        const int i = lane;
        float y  = sp[i * 5 + 0];
        float x  = sp[i * 5 + 1];
        float al = sp[i * 5 + 2];
        float be = sp[i * 5 + 3];
        float ga = sp[i * 5 + 4];
        float dy = rowc - y;
        float k2 = be;
        float k1 = fmaf(ga, dy, -2.0f * be * x);
        float m  = fmaf(al, dy, -(ga * x));
        float k0 = fmaf(m, dy, be * x * x);

        float e0 = k0;
        float e1 = k2 + k1 + k0;
        float emaxv = k0 - __fdividef(k1 * k1, 4.0f * k2);   // vertex value (>= k0)
        float wv = -0.5f * __fdividef(k1, k2);
        float emax = (wv > 0.0f && wv < 1.0f) ? emaxv : fmaxf(e0, e1);
        float emin = fminf(e0, e1);
        dead = (emax < TH_DEAD);
        poly = (emin >= TH_POLY);
        // alive interval (e >= -36): [wv-h, wv+h]
        float h = sqrtf(__fdividef(fmaxf(emaxv - TH_DEAD, 0.0f), -k2));
        lo = wv - h;
        hi = wv + h;
    }
    const unsigned deadm = __ballot_sync(0xffffffffu, (lane < NB) && dead) & 0xffu;
    const unsigned polym = __ballot_sync(0xffffffffu, (lane < NB) && poly) & 0xffu;
    const int istart = 32 - __clz(deadm);   // 0 if no dead blob

    float lo36[NB], hi36[NB];
    #pragma unroll
    for (int i = 0; i < NB; i++) {
        lo36[i] = __shfl_sync(0xffffffffu, lo, i);
        hi36[i] = __shfl_sync(0xffffffffu, hi, i);
    }

    // pixel-pair coordinates per chunk
    ull ww[NC];
    ull ximg[NC];
    #pragma unroll
    for (int c = 0; c < NC; c++) {
        float w0 = ((float)(c * 64 + 2 * lane) + 0.5f) * invT;
        ww[c]   = pk2(w0, w0 + invT);
        ximg[c] = 0ull;
    }

    const ull P5 = pk2(C5H, C5H), P4 = pk2(C4H, C4H), P3 = pk2(C3H, C3H);
    const ull P2 = pk2(C2H, C2H), P1 = pk2(C1H, C1H), P0 = pk2(C0H, C0H);

#define BLOB_BODY(i)                                                          \
    do {                                                                      \
        ull k2p = pk2(K2[i], K2[i]);                                          \
        ull k1p = pk2(K1[i], K1[i]);                                          \
        if (polym & (1u << (i))) {                                            \
            float k0s = K0[i] + 1.0f;                                         \
            ull k0p = pk2(k0s, k0s);                                          \
            _Pragma("unroll")                                                 \
            for (int c = 0; c < NC; c++) {                                    \
                ull u = fma2(fma2(k2p, ww[c], k1p), ww[c], k0p);              \
                ull p = fma2(P5, u, P4);                                      \
                p = fma2(p, u, P3);                                           \
                p = fma2(p, u, P2);                                           \
                p = fma2(p, u, P1);                                           \
                p = fma2(p, u, P0);                                           \
                ximg[c] = fma2(ximg[c], p, p);                                \
            }                                                                 \
        } else {                                                              \
            ull k0p = pk2(K0[i], K0[i]);                                      \
            _Pragma("unroll")                                                 \
            for (int c = 0; c < NC; c++) {                                    \
                float wc0 = ((float)(c * 64) + 0.5f) * invT;                  \
                float wc1 = ((float)(c * 64) + 63.5f) * invT;                 \
                if (wc1 < lo36[i] || wc0 > hi36[i]) {                         \
                    ximg[c] = 0ull;                                           \
                } else {                                                      \
                    ull e = fma2(fma2(k2p, ww[c], k1p), ww[c], k0p);          \
                    float ex, ey, cx, cy;                                     \
                    upk2(ex, ey, e);                                          \
                    asm("ex2.approx.ftz.f32 %0, %1;" : "=f"(cx) : "f"(ex));   \
                    asm("ex2.approx.ftz.f32 %0, %1;" : "=f"(cy) : "f"(ey));   \
                    ull cur = pk2(cx, cy);                                    \
                    ximg[c] = fma2(ximg[c], cur, cur);                        \
                }                                                             \
            }                                                                 \
        }                                                                     \
    } while (0)

    switch (istart) {
        case 0: BLOB_BODY(0);
        case 1: BLOB_BODY(1);
        case 2: BLOB_BODY(2);
        case 3: BLOB_BODY(3);
        case 4: BLOB_BODY(4);
        case 5: BLOB_BODY(5);
        case 6: BLOB_BODY(6);
        case 7: BLOB_BODY(7);
        default: break;   // istart == 8: whole row is ~0
    }
#undef BLOB_BODY

    float* orow = out + ((size_t)b * T + row) * T;
    #pragma unroll
    for (int c = 0; c < NC; c++) {
        float ix, iy;
        upk2(ix, iy, ximg[c]);
        reinterpret_cast<float2*>(orow + c * 64)[lane] = make_float2(ix, iy);
    }
}

// ---------------------------------------------------------------------------
// Generic fallback splat (round-2 kernel, known correct for any T).
// ---------------------------------------------------------------------------
__global__ void __launch_bounds__(256) splat_kernel(float* __restrict__ out,
                                                    int B, int T, float invT)
{
    const int b    = blockIdx.y;
    const int tid  = threadIdx.x;
    const int lane = tid & 31;
    const int r    = tid >> 5;
    const int row  = blockIdx.x * 8 + r;

    __shared__ float sp[NB * 5];
    if (tid < NB * 5) {
        int i = tid / 5, f = tid - i * 5;
        sp[tid] = g_params[((size_t)i * B + b) * 5 + f];
    }
    __syncthreads();
    if (row >= T) return;

    const float rowc = ((float)row + 0.5f) * invT;

    float K2[NB], K1[NB], K0[NB];
    #pragma unroll
    for (int i = 0; i < NB; i++) {
        float y  = sp[i * 5 + 0];
        float x  = sp[i * 5 + 1];
        float al = sp[i * 5 + 2];
        float be = sp[i * 5 + 3];
        float ga = sp[i * 5 + 4];
        float dy = rowc - y;
        K2[i] = be;
        K1[i] = fmaf(ga, dy, -2.0f * be * x);
        float m = fmaf(al, dy, -(ga * x));
        K0[i] = fmaf(m, dy, be * x * x);
    }

    float* orow = out + ((size_t)b * T + row) * T;
    const int nj = (T + 31) >> 5;

    for (int j = 0; j < nj; j++) {
        int col = lane + (j << 5);
        if (col >= T) break;
        float w = ((float)col + 0.5f) * invT;
        float img = 0.0f;
        #pragma unroll
        for (int i = 0; i < NB; i++) {
            float e = fmaf(fmaf(K2[i], w, K1[i]), w, K0[i]);
            float cur;
            asm("ex2.approx.ftz.f32 %0, %1;" : "=f"(cur) : "f"(e));
            img = fmaf(img, cur, cur);
        }
        orow[col] = img;
    }
}

// ---------------------------------------------------------------------------
extern "C" void kernel_launch(void* const* d_in, const int* in_sizes, int n_in,
                              void* d_out, int out_size)
{
    const float* positions = (const float*)d_in[0];
    const float* W1 = (const float*)d_in[1];
    const float* b1 = (const float*)d_in[2];
    const float* W2 = (const float*)d_in[3];
    const float* b2 = (const float*)d_in[4];
    const float* W3 = (const float*)d_in[5];
    const float* b3 = (const float*)d_in[6];
    const float* scale = (const float*)d_in[n_in - 1];

    int B = in_sizes[0] / 6;
    if (B > MAX_B) B = MAX_B;
    int T = (int)(sqrt((double)out_size / (double)B) + 0.5);
    float invT = 1.0f / (float)T;

    dim3 egrid((B + 3) / 4, NB);
    dim3 eblock(64, 4);
    encode_kernel<<<egrid, eblock>>>(positions, W1, b1, W2, b2, W3, b3, scale, B);

    dim3 sgrid((T + 7) / 8, B);
    if (T == 256)
        splat_fast<4><<<sgrid, 256>>>((float*)d_out, B, T, invT);
    else if (T == 128)
        splat_fast<2><<<sgrid, 256>>>((float*)d_out, B, T, invT);
    else
        splat_kernel<<<sgrid, 256>>>((float*)d_out, B, T, invT);
}

// round 6
// speedup vs baseline: 1.4916x; 1.2437x over previous
#include <cuda_runtime.h>
#include <math.h>

#define NB 8

__constant__ float c_START_Y[NB] = {0.1f, 0.2f, 0.3f, 0.4f, 0.5f, 0.6f, 0.7f, 0.8f};
__constant__ float c_START_X[NB] = {0.8f, 0.7f, 0.6f, 0.5f, 0.4f, 0.3f, 0.2f, 0.1f};
__constant__ int   c_SIDE[NB]    = {1, 0, 1, 0, 1, 0, 1, 0};

#define MAX_B 4096
__device__ float g_params[NB * MAX_B * 5];

__device__ __forceinline__ float sigmoidf_(float v) {
    return 1.0f / (1.0f + __expf(-v));
}

// ---------------- f32x2 packed helpers (Blackwell FFMA2) --------------------
typedef unsigned long long ull;
__device__ __forceinline__ ull pk2(float x, float y) {
    ull r; asm("mov.b64 %0, {%1,%2};" : "=l"(r) : "f"(x), "f"(y)); return r;
}
__device__ __forceinline__ void upk2(float& x, float& y, ull v) {
    asm("mov.b64 {%0,%1}, %2;" : "=f"(x), "=f"(y) : "l"(v));
}
__device__ __forceinline__ ull fma2(ull a, ull b, ull c) {
    ull d; asm("fma.rn.f32x2 %0, %1, %2, %3;" : "=l"(d) : "l"(a), "l"(b), "l"(c)); return d;
}
__device__ __forceinline__ ull add2(ull a, ull b) {
    ull d; asm("add.rn.f32x2 %0, %1, %2;" : "=l"(d) : "l"(a), "l"(b)); return d;
}
__device__ __forceinline__ ull mul2(ull a, ull b) {
    ull d; asm("mul.rn.f32x2 %0, %1, %2;" : "=l"(d) : "l"(a), "l"(b)); return d;
}

// ---------------------------------------------------------------------------
// Encode: per-blob MLP -> quadratic-form splat coefficients (unchanged, passes)
// ---------------------------------------------------------------------------
__global__ void encode_kernel(const float* __restrict__ positions,
                              const float* __restrict__ W1, const float* __restrict__ b1,
                              const float* __restrict__ W2, const float* __restrict__ b2,
                              const float* __restrict__ W3, const float* __restrict__ b3,
                              const float* __restrict__ scale_ptr, int B)
{
    const int i  = blockIdx.y;
    const int ty = threadIdx.y;
    const int k  = threadIdx.x;
    const int b  = blockIdx.x * 4 + ty;
    const bool valid = (b < B);

    __shared__ float sh_h[4][64];
    __shared__ float sh_bd[4][5];

    float h = 0.0f;
    if (valid) {
        const float* p = positions + (size_t)b * 6 + (c_SIDE[i] ? 0 : 3);
        float p0 = p[0] * 100.0f, p1 = p[1] * 100.0f, p2 = p[2] * 100.0f;
        const float* w1 = W1 + (size_t)i * 3 * 64;
        h = fmaf(p0, w1[k], fmaf(p1, w1[64 + k], fmaf(p2, w1[128 + k], b1[i * 64 + k])));
        h = fmaxf(h, 0.0f);
    }
    sh_h[ty][k] = h;
    __syncthreads();

    float acc = b2[i * 64 + k];
    {
        const float* w2 = W2 + (size_t)i * 64 * 64 + k;
        #pragma unroll 8
        for (int hh = 0; hh < 64; hh++)
            acc = fmaf(sh_h[ty][hh], w2[hh * 64], acc);
        acc = fmaxf(acc, 0.0f);
    }
    __syncthreads();
    sh_h[ty][k] = acc;
    __syncthreads();

    if (k < 5) {
        float o = b3[i * 5 + k];
        const float* w3 = W3 + (size_t)i * 64 * 5 + k;
        #pragma unroll 8
        for (int hh = 0; hh < 64; hh++)
            o = fmaf(sh_h[ty][hh], w3[hh * 5], o);
        sh_bd[ty][k] = o;
    }
    __syncthreads();

    if (k == 0 && valid) {
        float bd0 = sh_bd[ty][0], bd1 = sh_bd[ty][1], bd2 = sh_bd[ty][2];
        float bd3 = sh_bd[ty][3], bd4 = sh_bd[ty][4];
        float scale = *scale_ptr;

        float y  = sigmoidf_(bd0) + c_START_Y[i];
        float x  = sigmoidf_(bd1) + c_START_X[i];
        float s  = (bd2 + 0.05f) * scale;
        float a  = 0.5f + sigmoidf_(bd3) * 1.5f;
        float th = sigmoidf_(bd4) * 3.14159265358979323846f;

        float sa = s * a + 1e-6f;
        float sb = s / (a + 1e-6f) + 1e-6f;
        float A  = 0.5f / (sa * sa);
        float Bq = 0.5f / (sb * sb);

        float sn, c;
        sincosf(th, &sn, &c);

        const float L = 1.4426950408889634f;
        float al = -L * (A * c * c + Bq * sn * sn);
        float be = -L * (A * sn * sn + Bq * c * c);
        float ga = -2.0f * L * (A - Bq) * c * sn;

        float* o = g_params + ((size_t)i * B + b) * 5;
        o[0] = y; o[1] = x; o[2] = al; o[3] = be; o[4] = ga;
    }
}

// ---------------------------------------------------------------------------
// Splat: warp = row, lane = f32x2 pixel pair, chunk loop (64 px) not unrolled.
// Static pipe split: blobs in TRICK_MASK use FMA-only exp2 (magic-number range
// reduction + deg-4 poly), others use ex2.approx (MUFU). No data-dependent
// branches in the hot loop.
// ---------------------------------------------------------------------------

#define TRICK_MASK 0x11u   // blobs 0,4 on the FMA path; 6 blobs on MUFU

// deg-4 Taylor of 2^f on f in [-0.5, 0.5]  (rel err <= 4.5e-5)
#define E2C0 1.0000000000f
#define E2C1 0.6931471806f
#define E2C2 0.2402265070f
#define E2C3 0.0555041087f
#define E2C4 0.0096181291f

#define MAGIC 12582912.0f   // 1.5 * 2^23

template<int NC>
__global__ void __launch_bounds__(256) splat_fast(float* __restrict__ out,
                                                  int B, int T, float invT)
{
    const int b    = blockIdx.y;
    const int tid  = threadIdx.x;
    const int lane = tid & 31;
    const int r    = tid >> 5;
    const int row  = blockIdx.x * 8 + r;

    __shared__ float sp[NB * 5];
    if (tid < NB * 5) {
        int i = tid / 5, f = tid - i * 5;
        sp[tid] = g_params[((size_t)i * B + b) * 5 + f];
    }
    __syncthreads();
    if (row >= T) return;

    const float rowc = ((float)row + 0.5f) * invT;

    // per-blob row quadratic e(w) = K2 w^2 + K1 w + K0  (e <= 0), warp-uniform
    float K2[NB], K1[NB], K0[NB];
    #pragma unroll
    for (int i = 0; i < NB; i++) {
        float y  = sp[i * 5 + 0];
        float x  = sp[i * 5 + 1];
        float al = sp[i * 5 + 2];
        float be = sp[i * 5 + 3];
        float ga = sp[i * 5 + 4];
        float dy = rowc - y;
        K2[i] = be;
        K1[i] = fmaf(ga, dy, -2.0f * be * x);
        float m = fmaf(al, dy, -(ga * x));
        K0[i] = fmaf(m, dy, be * x * x);
    }

    const ull M2    = pk2(MAGIC, MAGIC);
    const ull NEGM2 = pk2(-MAGIC, -MAGIC);
    const ull NEG1  = pk2(-1.0f, -1.0f);
    const ull P4 = pk2(E2C4, E2C4), P3 = pk2(E2C3, E2C3), P2 = pk2(E2C2, E2C2);
    const ull P1 = pk2(E2C1, E2C1), P0 = pk2(E2C0, E2C0);

    float2* orow = reinterpret_cast<float2*>(out + ((size_t)b * T + row) * T);

    const float wbase = ((float)(2 * lane) + 0.5f) * invT;
    const float wstep = 64.0f * invT;

    #pragma unroll 1
    for (int c = 0; c < NC; c++) {
        float w0 = fmaf((float)c, wstep, wbase);
        ull w   = pk2(w0, w0 + invT);
        ull img = 0ull;

        #pragma unroll
        for (int i = 0; i < NB; i++) {
            ull k2p = pk2(K2[i], K2[i]);
            ull k1p = pk2(K1[i], K1[i]);
            ull k0p = pk2(K0[i], K0[i]);
            ull e = fma2(fma2(k2p, w, k1p), w, k0p);
            ull cur;
            if ((TRICK_MASK >> i) & 1) {
                // ---- FMA-pipe exp2 (all e <= 0) ----
                float elo, ehi;
                upk2(elo, ehi, e);
                elo = fmaxf(elo, -126.0f);
                ehi = fmaxf(ehi, -126.0f);
                ull ec = pk2(elo, ehi);
                ull t  = add2(ec, M2);                 // MAGIC + round(e)
                ull kf = add2(t, NEGM2);               // k = round(e), exact
                ull f  = fma2(kf, NEG1, ec);           // f = e - k in [-0.5, 0.5], exact
                float tlo, thi;
                upk2(tlo, thi, t);
                unsigned slo = (__float_as_uint(tlo) << 23) + 0x3F800000u;
                unsigned shi = (__float_as_uint(thi) << 23) + 0x3F800000u;
                ull sc = pk2(__uint_as_float(slo), __uint_as_float(shi));  // 2^k
                ull p = fma2(P4, f, P3);
                p = fma2(p, f, P2);
                p = fma2(p, f, P1);
                p = fma2(p, f, P0);
                cur = mul2(p, sc);                     // 2^k * 2^f
            } else {
                // ---- MUFU exp2 ----
                float ex, ey, cx, cy;
                upk2(ex, ey, e);
                asm("ex2.approx.ftz.f32 %0, %1;" : "=f"(cx) : "f"(ex));
                asm("ex2.approx.ftz.f32 %0, %1;" : "=f"(cy) : "f"(ey));
                cur = pk2(cx, cy);
            }
            img = fma2(img, cur, cur);                 // reference blend order
        }

        float ix, iy;
        upk2(ix, iy, img);
        orow[c * 32 + lane] = make_float2(ix, iy);
    }
}

// ---------------------------------------------------------------------------
// Generic fallback splat (round-2 kernel, known correct for any T).
// ---------------------------------------------------------------------------
__global__ void __launch_bounds__(256) splat_kernel(float* __restrict__ out,
                                                    int B, int T, float invT)
{
    const int b    = blockIdx.y;
    const int tid  = threadIdx.x;
    const int lane = tid & 31;
    const int r    = tid >> 5;
    const int row  = blockIdx.x * 8 + r;

    __shared__ float sp[NB * 5];
    if (tid < NB * 5) {
        int i = tid / 5, f = tid - i * 5;
        sp[tid] = g_params[((size_t)i * B + b) * 5 + f];
    }
    __syncthreads();
    if (row >= T) return;

    const float rowc = ((float)row + 0.5f) * invT;

    float K2[NB], K1[NB], K0[NB];
    #pragma unroll
    for (int i = 0; i < NB; i++) {
        float y  = sp[i * 5 + 0];
        float x  = sp[i * 5 + 1];
        float al = sp[i * 5 + 2];
        float be = sp[i * 5 + 3];
        float ga = sp[i * 5 + 4];
        float dy = rowc - y;
        K2[i] = be;
        K1[i] = fmaf(ga, dy, -2.0f * be * x);
        float m = fmaf(al, dy, -(ga * x));
        K0[i] = fmaf(m, dy, be * x * x);
    }

    float* orow = out + ((size_t)b * T + row) * T;
    const int nj = (T + 31) >> 5;

    for (int j = 0; j < nj; j++) {
        int col = lane + (j << 5);
        if (col >= T) break;
        float w = ((float)col + 0.5f) * invT;
        float img = 0.0f;
        #pragma unroll
        for (int i = 0; i < NB; i++) {
            float e = fmaf(fmaf(K2[i], w, K1[i]), w, K0[i]);
            float cur;
            asm("ex2.approx.ftz.f32 %0, %1;" : "=f"(cur) : "f"(e));
            img = fmaf(img, cur, cur);
        }
        orow[col] = img;
    }
}

// ---------------------------------------------------------------------------
extern "C" void kernel_launch(void* const* d_in, const int* in_sizes, int n_in,
                              void* d_out, int out_size)
{
    const float* positions = (const float*)d_in[0];
    const float* W1 = (const float*)d_in[1];
    const float* b1 = (const float*)d_in[2];
    const float* W2 = (const float*)d_in[3];
    const float* b2 = (const float*)d_in[4];
    const float* W3 = (const float*)d_in[5];
    const float* b3 = (const float*)d_in[6];
    const float* scale = (const float*)d_in[n_in - 1];

    int B = in_sizes[0] / 6;
    if (B > MAX_B) B = MAX_B;
    int T = (int)(sqrt((double)out_size / (double)B) + 0.5);
    float invT = 1.0f / (float)T;

    dim3 egrid((B + 3) / 4, NB);
    dim3 eblock(64, 4);
    encode_kernel<<<egrid, eblock>>>(positions, W1, b1, W2, b2, W3, b3, scale, B);

    dim3 sgrid((T + 7) / 8, B);
    if (T == 256)
        splat_fast<4><<<sgrid, 256>>>((float*)d_out, B, T, invT);
    else if (T == 128)
        splat_fast<2><<<sgrid, 256>>>((float*)d_out, B, T, invT);
    else
        splat_kernel<<<sgrid, 256>>>((float*)d_out, B, T, invT);
}